// round 7
// baseline (speedup 1.0000x reference)
#include <cuda_runtime.h>
#include <math.h>

#define DIMC 192
#define HEADS 6
#define HD 32
#define WS 8
#define SSH 4
#define NTOK 64
#define BATCH 4
#define HIMG 256
#define WIMG 256
#define NWIN 4096            // total windows (B * 32 * 32)
#define SCALE 0.17677669529663687f   // 32^-0.5

// ---------------- scratch (device globals; no allocations allowed) ----------
__device__ float g_qkv[(size_t)NWIN * NTOK * 3 * DIMC];  // layout [win][o(576)][t(64)]
__device__ float g_o  [(size_t)NWIN * NTOK * DIMC];      // layout [win][c(192)][t(64)]
__device__ float g_wT [DIMC * 3 * DIMC];                 // qkv_w transposed: [k][o]
__device__ float g_pT [DIMC * DIMC];                     // proj_w transposed: [k][o]

// ---------------- kernel 0: weight transpose --------------------------------
__global__ void transpose_weights(const float* __restrict__ qkv_w,
                                  const float* __restrict__ proj_w) {
    int idx = blockIdx.x * 256 + threadIdx.x;
    if (idx < 576 * DIMC) {
        int o = idx / DIMC, k = idx % DIMC;
        g_wT[k * 576 + o] = qkv_w[idx];
    }
    if (idx < DIMC * DIMC) {
        int o = idx / DIMC, k = idx % DIMC;
        g_pT[k * DIMC + o] = proj_w[idx];
    }
}

// ---------------- kernel 1: gather + QKV GEMM --------------------------------
// One CTA per window. Xs holds the shifted window, channel-major: Xs[k][t].
// Computes out[t][o] = sum_k Xs[k][t] * wT[k][o] + b[o], o in 9 chunks of 64.
__global__ __launch_bounds__(256) void qkv_kernel(const float* __restrict__ x,
                                                  const float* __restrict__ qkv_b) {
    __shared__ float Xs[DIMC][NTOK];   // 48KB
    int win = blockIdx.x;
    int b  = win >> 10;
    int wy = (win >> 5) & 31;
    int wx = win & 31;
    int tid = threadIdx.x;

    int y0 = wy * 8 + SSH;
    int x0 = wx * 8 + SSH;
    for (int idx = tid; idx < DIMC * NTOK; idx += 256) {
        int t = idx & 63, c = idx >> 6;
        int yy = (y0 + (t >> 3)) & 255;
        int xx = (x0 + (t & 7)) & 255;
        Xs[c][t] = x[(size_t)(b * DIMC + c) * 65536 + yy * 256 + xx];
    }
    __syncthreads();

    int ti = tid >> 4;            // token group (4 tokens)
    int tj = tid & 15;            // output group (4 outputs)
    int t0 = ti * 4;
    float* op = g_qkv + (size_t)win * (NTOK * 576);
    const float* __restrict__ wT = g_wT;

    for (int chunk = 0; chunk < 9; chunk++) {
        int obase = chunk * 64 + tj * 4;
        float4 bv = *(const float4*)&qkv_b[obase];
        float4 a0 = make_float4(bv.x, bv.x, bv.x, bv.x);   // output obase+0, tokens t0..t0+3
        float4 a1 = make_float4(bv.y, bv.y, bv.y, bv.y);
        float4 a2 = make_float4(bv.z, bv.z, bv.z, bv.z);
        float4 a3 = make_float4(bv.w, bv.w, bv.w, bv.w);
        #pragma unroll 4
        for (int k = 0; k < DIMC; k++) {
            float4 a = *(const float4*)&Xs[k][t0];
            float4 w = *(const float4*)&wT[k * 576 + obase];
            a0.x += a.x * w.x; a0.y += a.y * w.x; a0.z += a.z * w.x; a0.w += a.w * w.x;
            a1.x += a.x * w.y; a1.y += a.y * w.y; a1.z += a.z * w.y; a1.w += a.w * w.y;
            a2.x += a.x * w.z; a2.y += a.y * w.z; a2.z += a.z * w.z; a2.w += a.w * w.z;
            a3.x += a.x * w.w; a3.y += a.y * w.w; a3.z += a.z * w.w; a3.w += a.w * w.w;
        }
        *(float4*)&op[(size_t)(obase + 0) * 64 + t0] = a0;
        *(float4*)&op[(size_t)(obase + 1) * 64 + t0] = a1;
        *(float4*)&op[(size_t)(obase + 2) * 64 + t0] = a2;
        *(float4*)&op[(size_t)(obase + 3) * 64 + t0] = a3;
    }
}

// ---------------- kernel 2: windowed attention -------------------------------
// grid (4096, 6), 64 threads. Thread i owns query row i of its (window, head).
__global__ __launch_bounds__(64) void attn_kernel(const float* __restrict__ rpb_table) {
    __shared__ float Ks[HD][NTOK];     // [d][j] 8KB
    __shared__ float Vs[HD][NTOK];     // [d][j] 8KB
    __shared__ float rpbs[225 * HEADS];
    __shared__ int   regsh[NTOK];

    int win = blockIdx.x;
    int h   = blockIdx.y;
    int wy = (win >> 5) & 31;
    int wx = win & 31;
    int i = threadIdx.x;

    const float* base = g_qkv + (size_t)win * (NTOK * 576);
    const float* Kg = base + (size_t)(192 + h * HD) * 64;
    const float* Vg = base + (size_t)(384 + h * HD) * 64;
    for (int idx = i; idx < HD * NTOK / 4; idx += 64) {
        ((float4*)Ks)[idx] = ((const float4*)Kg)[idx];
        ((float4*)Vs)[idx] = ((const float4*)Vg)[idx];
    }
    for (int idx = i; idx < 225 * HEADS; idx += 64) rpbs[idx] = rpb_table[idx];

    int iy = i >> 3, ix = i & 7;
    {
        // region id in shifted coordinates (Swin shift mask)
        int yt = wy * 8 + iy;
        int xt = wx * 8 + ix;
        int ry = (yt < HIMG - WS) ? 0 : ((yt < HIMG - SSH) ? 1 : 2);
        int rx = (xt < WIMG - WS) ? 0 : ((xt < WIMG - SSH) ? 1 : 2);
        regsh[i] = ry * 3 + rx;
    }

    float q[HD];
    const float* Qg = base + (size_t)(h * HD) * 64;
    #pragma unroll
    for (int d = 0; d < HD; d++) q[d] = Qg[d * 64 + i];

    __syncthreads();
    int regi = regsh[i];

    float l = 0.f;
    float acc[HD];
    #pragma unroll
    for (int d = 0; d < HD; d++) acc[d] = 0.f;

    for (int j4 = 0; j4 < NTOK; j4 += 4) {
        float s0 = 0.f, s1 = 0.f, s2 = 0.f, s3 = 0.f;
        #pragma unroll
        for (int d = 0; d < HD; d++) {
            float4 kx = *(const float4*)&Ks[d][j4];
            s0 += q[d] * kx.x; s1 += q[d] * kx.y;
            s2 += q[d] * kx.z; s3 += q[d] * kx.w;
        }
        float e0, e1, e2, e3;
        {
            int j;
            float bias, m;
            j = j4 + 0;
            bias = rpbs[((iy - (j >> 3) + 7) * 15 + (ix - (j & 7) + 7)) * HEADS + h];
            m = (regi != regsh[j]) ? -100.f : 0.f;
            e0 = expf(s0 * SCALE + bias + m);
            j = j4 + 1;
            bias = rpbs[((iy - (j >> 3) + 7) * 15 + (ix - (j & 7) + 7)) * HEADS + h];
            m = (regi != regsh[j]) ? -100.f : 0.f;
            e1 = expf(s1 * SCALE + bias + m);
            j = j4 + 2;
            bias = rpbs[((iy - (j >> 3) + 7) * 15 + (ix - (j & 7) + 7)) * HEADS + h];
            m = (regi != regsh[j]) ? -100.f : 0.f;
            e2 = expf(s2 * SCALE + bias + m);
            j = j4 + 3;
            bias = rpbs[((iy - (j >> 3) + 7) * 15 + (ix - (j & 7) + 7)) * HEADS + h];
            m = (regi != regsh[j]) ? -100.f : 0.f;
            e3 = expf(s3 * SCALE + bias + m);
        }
        l += e0 + e1 + e2 + e3;
        #pragma unroll
        for (int d = 0; d < HD; d++) {
            float4 vx = *(const float4*)&Vs[d][j4];
            acc[d] += e0 * vx.x + e1 * vx.y + e2 * vx.z + e3 * vx.w;
        }
    }

    float invl = 1.f / l;
    float* Og = g_o + (size_t)win * (NTOK * DIMC) + (size_t)(h * HD) * 64;
    #pragma unroll
    for (int d = 0; d < HD; d++) Og[d * 64 + i] = acc[d] * invl;
}

// ---------------- kernel 3: proj GEMM + reverse-shift scatter ----------------
__global__ __launch_bounds__(256) void proj_kernel(const float* __restrict__ proj_b,
                                                   float* __restrict__ out) {
    __shared__ float Os[DIMC * NTOK];  // [c][t], 48KB
    int win = blockIdx.x;
    int b  = win >> 10;
    int wy = (win >> 5) & 31;
    int wx = win & 31;
    int tid = threadIdx.x;

    const float* src = g_o + (size_t)win * (NTOK * DIMC);
    for (int idx = tid; idx < DIMC * NTOK / 4; idx += 256)
        ((float4*)Os)[idx] = ((const float4*)src)[idx];
    __syncthreads();

    int ti = tid >> 4;
    int tj = tid & 15;
    int t0 = ti * 4;
    // destination pixels of this thread's 4 tokens (same row, contiguous, no
    // wrap inside the group: x base is always ≡ 0 mod 4 and ≤ 252 after &255)
    int yy = (wy * 8 + (t0 >> 3) + SSH) & 255;
    int xx = (wx * 8 + (t0 & 7) + SSH) & 255;
    const float* __restrict__ pT = g_pT;

    for (int chunk = 0; chunk < 3; chunk++) {
        int obase = chunk * 64 + tj * 4;
        float4 bv = *(const float4*)&proj_b[obase];
        float4 a0 = make_float4(bv.x, bv.x, bv.x, bv.x);
        float4 a1 = make_float4(bv.y, bv.y, bv.y, bv.y);
        float4 a2 = make_float4(bv.z, bv.z, bv.z, bv.z);
        float4 a3 = make_float4(bv.w, bv.w, bv.w, bv.w);
        #pragma unroll 4
        for (int k = 0; k < DIMC; k++) {
            float4 a = *(const float4*)&Os[k * 64 + t0];
            float4 w = *(const float4*)&pT[k * DIMC + obase];
            a0.x += a.x * w.x; a0.y += a.y * w.x; a0.z += a.z * w.x; a0.w += a.w * w.x;
            a1.x += a.x * w.y; a1.y += a.y * w.y; a1.z += a.z * w.y; a1.w += a.w * w.y;
            a2.x += a.x * w.z; a2.y += a.y * w.z; a2.z += a.z * w.z; a2.w += a.w * w.z;
            a3.x += a.x * w.w; a3.y += a.y * w.w; a3.z += a.z * w.w; a3.w += a.w * w.w;
        }
        size_t pix = (size_t)yy * 256 + xx;
        *(float4*)&out[(size_t)(b * DIMC + obase + 0) * 65536 + pix] = a0;
        *(float4*)&out[(size_t)(b * DIMC + obase + 1) * 65536 + pix] = a1;
        *(float4*)&out[(size_t)(b * DIMC + obase + 2) * 65536 + pix] = a2;
        *(float4*)&out[(size_t)(b * DIMC + obase + 3) * 65536 + pix] = a3;
    }
}

// ---------------- launch ------------------------------------------------------
extern "C" void kernel_launch(void* const* d_in, const int* in_sizes, int n_in,
                              void* d_out, int out_size) {
    const float* x      = (const float*)d_in[0];
    const float* qkv_w  = (const float*)d_in[1];
    const float* qkv_b  = (const float*)d_in[2];
    const float* proj_w = (const float*)d_in[3];
    const float* proj_b = (const float*)d_in[4];
    const float* rpb    = (const float*)d_in[5];
    float* out = (float*)d_out;

    transpose_weights<<<432, 256>>>(qkv_w, proj_w);
    qkv_kernel<<<NWIN, 256>>>(x, qkv_b);
    attn_kernel<<<dim3(NWIN, HEADS), 64>>>(rpb);
    proj_kernel<<<NWIN, 256>>>(proj_b, out);
}